// round 14
// baseline (speedup 1.0000x reference)
#include <cuda_runtime.h>

// ---------------------------------------------------------------------------
// Quantum multi-head attention, NQ=4, DIM=16, B=32, S=2048.
// Real-amplitude circuit: amp(i) = (-i)^popcount(i) * u_i, u real; RX = Givens
// rotation, CNOT = permutation, probs = u^2.
// K0: prep — cos/sin of uniform weights (Q,K,V,C) once.
// K1: per-token circuits -> Q(pre-scaled), K, V.
// K2: attention partials. QPT=1, KSPLIT=2 (minimal partial traffic: 5 MB vs
//     84 MB at KSPLIT=32 — reduce was 13.3us DRAM-bound). Pre-packed key-pair
//     transposed f32x2 smem tiles; one fma2 chain = 2 dots; one f16x2 EX2
//     per 2 keys.
// K3: combine 2 partials, normalize, final circuit -> out.
// ---------------------------------------------------------------------------

#define B 32
#define S 2048
#define NTOK (B * S)          // 65536
#define KSPLIT 2
#define KCHUNK (S / KSPLIT)   // 1024 keys per block
#define TILE 128              // keys per smem refill
#define TPAIR (TILE / 2)      // 64 pairs per tile

__device__ float g_Q[NTOK * 4];
__device__ float g_K[NTOK * 4];
__device__ float g_V[NTOK * 4];
__device__ float4 g_p0[NTOK * KSPLIT];   // (ssum, a0, a1, a2)
__device__ float  g_p1[NTOK * KSPLIT];   // a3
__device__ float2 g_w[16];               // cos/sin(w/2): [0..3]=Q,[4..7]=K,[8..11]=V,[12..15]=C

typedef unsigned long long u64;

__device__ __forceinline__ u64 mul2(u64 a, u64 b) {
    u64 d; asm("mul.rn.f32x2 %0,%1,%2;" : "=l"(d) : "l"(a), "l"(b)); return d;
}
__device__ __forceinline__ u64 fma2(u64 a, u64 b, u64 c) {
    u64 d; asm("fma.rn.f32x2 %0,%1,%2,%3;" : "=l"(d) : "l"(a), "l"(b), "l"(c)); return d;
}
__device__ __forceinline__ u64 add2(u64 a, u64 b) {
    u64 d; asm("add.rn.f32x2 %0,%1,%2;" : "=l"(d) : "l"(a), "l"(b)); return d;
}
__device__ __forceinline__ float2 u2f(u64 u) {
    float2 f; asm("mov.b64 {%0,%1}, %2;" : "=f"(f.x), "=f"(f.y) : "l"(u)); return f;
}
__device__ __forceinline__ u64 f2u(float a, float b) {
    u64 u; asm("mov.b64 %0, {%1,%2};" : "=l"(u) : "f"(a), "f"(b)); return u;
}

// Both-keys exp2 in one MUFU op: f32x2 -> f16x2 -> ex2 -> two f32.
__device__ __forceinline__ u64 exp2_pair(u64 d2) {
    float2 df = u2f(d2);
    unsigned int hd, he;
    asm("cvt.rn.f16x2.f32 %0, %1, %2;" : "=r"(hd) : "f"(df.y), "f"(df.x));
    asm("ex2.approx.f16x2 %0, %1;" : "=r"(he) : "r"(hd));
    float ea, eb;
    asm("{ .reg .b16 l,h;\n\t"
        "  mov.b32 {l,h}, %2;\n\t"
        "  cvt.f32.f16 %0, l;\n\t"
        "  cvt.f32.f16 %1, h; }"
        : "=f"(ea), "=f"(eb) : "r"(he));
    return f2u(ea, eb);
}

// Real Givens rotation for RX on amplitude-mask M.
template <int M>
__device__ __forceinline__ void rx_real(float u[16], float c, float s) {
#pragma unroll
    for (int i = 0; i < 16; ++i) {
        if (i & M) continue;
        const int j = i | M;
        float ui = u[i], uj = u[j];
        u[i] = c * ui - s * uj;
        u[j] = c * uj + s * ui;
    }
}

// Circuit with precomputed weight cos/sin (wcs[q] = {cos, sin} of w_q/2).
__device__ __forceinline__ void run_circuit(const float ac[4], const float as_[4],
                                            const float2 wcs[4], float out[4]) {
    float u[16];
#pragma unroll
    for (int i = 0; i < 16; ++i) u[i] = 0.0f;
    u[0] = 1.0f;

    rx_real<8>(u, ac[0], as_[0]);
    rx_real<4>(u, ac[1], as_[1]);
    rx_real<2>(u, ac[2], as_[2]);
    rx_real<1>(u, ac[3], as_[3]);
    rx_real<8>(u, wcs[0].x, wcs[0].y);
    rx_real<4>(u, wcs[1].x, wcs[1].y);
    rx_real<2>(u, wcs[2].x, wcs[2].y);
    rx_real<1>(u, wcs[3].x, wcs[3].y);

#define SWAP_AMP(a, b) { float t = u[a]; u[a] = u[b]; u[b] = t; }
    SWAP_AMP(8, 12)  SWAP_AMP(9, 13)  SWAP_AMP(10, 14) SWAP_AMP(11, 15)   // CNOT(0,1)
    SWAP_AMP(4, 6)   SWAP_AMP(5, 7)   SWAP_AMP(12, 14) SWAP_AMP(13, 15)   // CNOT(1,2)
    SWAP_AMP(2, 3)   SWAP_AMP(6, 7)   SWAP_AMP(10, 11) SWAP_AMP(14, 15)   // CNOT(2,3)
    SWAP_AMP(1, 9)   SWAP_AMP(3, 11)  SWAP_AMP(5, 13)  SWAP_AMP(7, 15)    // CNOT(3,0)
#undef SWAP_AMP

    float p[16];
#pragma unroll
    for (int i = 0; i < 16; ++i) p[i] = u[i] * u[i];

    float a0 = p[0] + p[1],   d0 = p[0] - p[1];
    float a1 = p[2] + p[3],   d1 = p[2] - p[3];
    float a2 = p[4] + p[5],   d2 = p[4] - p[5];
    float a3 = p[6] + p[7],   d3 = p[6] - p[7];
    float a4 = p[8] + p[9],   d4 = p[8] - p[9];
    float a5 = p[10] + p[11], d5 = p[10] - p[11];
    float a6 = p[12] + p[13], d6 = p[12] - p[13];
    float a7 = p[14] + p[15], d7 = p[14] - p[15];
    out[3] = ((d0 + d1) + (d2 + d3)) + ((d4 + d5) + (d6 + d7));
    float b0 = a0 + a1, e0 = a0 - a1;
    float b1 = a2 + a3, e1 = a2 - a3;
    float b2 = a4 + a5, e2 = a4 - a5;
    float b3 = a6 + a7, e3 = a6 - a7;
    out[2] = (e0 + e1) + (e2 + e3);
    float c0 = b0 + b1, f0 = b0 - b1;
    float c1 = b2 + b3, f1 = b2 - b3;
    out[1] = f0 + f1;
    out[0] = c0 - c1;
}

// ---------------------------------------------------------------------------
// K0: precompute cos/sin of all uniform weights (one warp).
// ---------------------------------------------------------------------------
__global__ void prep_kernel(const float* __restrict__ wQ, const float* __restrict__ wK,
                            const float* __restrict__ wV, const float* __restrict__ wC) {
    int i = threadIdx.x;       // 0..15
    if (i < 16) {
        const float* src = (i < 4) ? wQ : (i < 8) ? wK : (i < 12) ? wV : wC;
        float ang = 0.5f * src[i & 3];
        float c, s;
        __sincosf(ang, &s, &c);
        g_w[i] = make_float2(c, s);
    }
}

// ---------------------------------------------------------------------------
// K1: token circuits. blockIdx.y selects which of {Q,K,V}.
// ---------------------------------------------------------------------------
__global__ void __launch_bounds__(128) qkv_kernel(const float4* __restrict__ x) {
    const int t = blockIdx.x * 128 + threadIdx.x;
    const int which = blockIdx.y;

    float4 a = x[t];
    float ac[4], as_[4];
    __sincosf(0.5f * a.x, &as_[0], &ac[0]);
    __sincosf(0.5f * a.y, &as_[1], &ac[1]);
    __sincosf(0.5f * a.z, &as_[2], &ac[2]);
    __sincosf(0.5f * a.w, &as_[3], &ac[3]);

    float* dst = (which == 0) ? g_Q : (which == 1) ? g_K : g_V;
    const float scale = (which == 0) ? (0.5f * 1.4426950408889634f) : 1.0f;

    float2 wcs[4];
#pragma unroll
    for (int q = 0; q < 4; ++q) wcs[q] = g_w[which * 4 + q];

    float o[4];
    run_circuit(ac, as_, wcs, o);
    reinterpret_cast<float4*>(dst)[t] =
        make_float4(o[0] * scale, o[1] * scale, o[2] * scale, o[3] * scale);
}

// ---------------------------------------------------------------------------
// K2: attention partials. grid (B, S/128, KSPLIT) = (32,16,2), 128 threads.
// Thread owns ONE query; streams KCHUNK=1024 keys in 8 smem tiles of 128 keys.
// smem tiles pre-packed key-pair transposed (f32x2 words):
//   s_kxy[p] = { (kx[2p],kx[2p+1]), (ky[2p],ky[2p+1]) }, s_kzw/s_vxy/s_vzw same.
// Inner per 2 keys: 4 LDS.128 + 4 fma2 (dual dot) + 1 f16x2 EX2 + 1 add2 +
// 4 fma2 (accum). f32 accumulation.
// ---------------------------------------------------------------------------
__global__ void __launch_bounds__(128) attn_kernel() {
    __shared__ ulonglong2 s_kxy[TPAIR], s_kzw[TPAIR], s_vxy[TPAIR], s_vzw[TPAIR];

    const int b  = blockIdx.x;
    const int qb = blockIdx.y * 128;
    const int kq = blockIdx.z;
    const int t  = threadIdx.x;
    const int w  = t >> 5, lane = t & 31;

    float4 qv = reinterpret_cast<const float4*>(g_Q)[b * S + qb + t];
    u64 qx = f2u(qv.x, qv.x), qy = f2u(qv.y, qv.y);
    u64 qz = f2u(qv.z, qv.z), qw_ = f2u(qv.w, qv.w);
    u64 ax = f2u(0.f, 0.f), ay = ax, az = ax, aw = ax, ss = ax;

    const float4* srcK = reinterpret_cast<const float4*>(g_K) + b * S + kq * KCHUNK;
    const float4* srcV = reinterpret_cast<const float4*>(g_V) + b * S + kq * KCHUNK;

    for (int tile = 0; tile < KCHUNK / TILE; ++tile) {
        __syncthreads();
        // Fill: warp w builds array w; lane handles pairs (lane, lane+32).
        {
            const float4* src = ((w < 2) ? srcK : srcV) + tile * TILE;
            ulonglong2* dst = (w == 0) ? s_kxy : (w == 1) ? s_kzw
                            : (w == 2) ? s_vxy : s_vzw;
#pragma unroll
            for (int pp = lane; pp < TPAIR; pp += 32) {
                float4 k0 = src[2 * pp];
                float4 k1 = src[2 * pp + 1];
                ulonglong2 pk;
                if (w & 1) { pk.x = f2u(k0.z, k1.z); pk.y = f2u(k0.w, k1.w); }
                else       { pk.x = f2u(k0.x, k1.x); pk.y = f2u(k0.y, k1.y); }
                dst[pp] = pk;
            }
        }
        __syncthreads();

#pragma unroll 8
        for (int p = 0; p < TPAIR; ++p) {
            ulonglong2 kxy = s_kxy[p];
            ulonglong2 kzw = s_kzw[p];
            ulonglong2 vxy = s_vxy[p];
            ulonglong2 vzw = s_vzw[p];
            u64 d2 = fma2(qw_, kzw.y,
                     fma2(qz, kzw.x,
                     fma2(qy, kxy.y, mul2(qx, kxy.x))));
            u64 e2 = exp2_pair(d2);
            ss = add2(ss, e2);
            ax = fma2(e2, vxy.x, ax);
            ay = fma2(e2, vxy.y, ay);
            az = fma2(e2, vzw.x, az);
            aw = fma2(e2, vzw.y, aw);
        }
    }

    const int base = ((b * KSPLIT + kq) << 11) + qb + t;
    float2 sx = u2f(ss);
    float2 x0 = u2f(ax), x1 = u2f(ay), x2 = u2f(az), x3 = u2f(aw);
    g_p0[base] = make_float4(sx.x + sx.y, x0.x + x0.y, x1.x + x1.y, x2.x + x2.y);
    g_p1[base] = x3.x + x3.y;
}

// ---------------------------------------------------------------------------
// K3: combine 2 partials, normalize, final circuit -> out.
// ---------------------------------------------------------------------------
__global__ void __launch_bounds__(128) reduce_kernel(float4* __restrict__ out) {
    int g = blockIdx.x * 128 + threadIdx.x;
    int b = g >> 11;
    int q = g & (S - 1);

    int i0 = ((b * KSPLIT + 0) << 11) + q;
    int i1 = ((b * KSPLIT + 1) << 11) + q;
    float4 p0 = g_p0[i0];
    float4 p1 = g_p0[i1];
    float ssum = p0.x + p1.x;
    float a0 = p0.y + p1.y, a1 = p0.z + p1.z, a2 = p0.w + p1.w;
    float a3 = g_p1[i0] + g_p1[i1];
    float inv = 1.0f / ssum;

    float cc[4], cs[4], o[4];
    __sincosf(0.5f * a0 * inv, &cs[0], &cc[0]);
    __sincosf(0.5f * a1 * inv, &cs[1], &cc[1]);
    __sincosf(0.5f * a2 * inv, &cs[2], &cc[2]);
    __sincosf(0.5f * a3 * inv, &cs[3], &cc[3]);

    float2 wcs[4];
#pragma unroll
    for (int i = 0; i < 4; ++i) wcs[i] = g_w[12 + i];

    run_circuit(cc, cs, wcs, o);
    out[g] = make_float4(o[0], o[1], o[2], o[3]);
}

// ---------------------------------------------------------------------------
extern "C" void kernel_launch(void* const* d_in, const int* in_sizes, int n_in,
                              void* d_out, int out_size) {
    (void)in_sizes; (void)n_in; (void)out_size;
    const float4* x  = (const float4*)d_in[0];
    const float*  wQ = (const float*)d_in[1];
    const float*  wK = (const float*)d_in[2];
    const float*  wV = (const float*)d_in[3];
    const float*  wC = (const float*)d_in[4];

    prep_kernel<<<1, 32>>>(wQ, wK, wV, wC);
    qkv_kernel<<<dim3(NTOK / 128, 3), 128>>>(x);
    attn_kernel<<<dim3(B, S / 128, KSPLIT), 128>>>();
    reduce_kernel<<<NTOK / 128, 128>>>((float4*)d_out);
}

// round 16
// speedup vs baseline: 1.1613x; 1.1613x over previous
#include <cuda_runtime.h>

// ---------------------------------------------------------------------------
// Quantum multi-head attention, NQ=4, DIM=16, B=32, S=2048.
// Real-amplitude circuit: amp(i) = (-i)^popcount(i) * u_i, u real; RX = Givens
// rotation, CNOT = permutation, probs = u^2.
// K0: prep — cos/sin of uniform weights (Q,K,V,C) once.
// K1: per-token circuits -> Q(pre-scaled), K, V.
// K2: attention partials. QPT=4, KSPLIT=16 (sweet spot: attn granularity of
//     the KSPLIT=32 config at half the partial DRAM traffic). Pre-packed
//     key-pair transposed f32x2 smem tiles; dual-dot fma2 chain; one f16x2
//     EX2 per 2 keys. Split into two launches so attn lands at ncu capture
//     position #4.
// K3: combine 16 partials, normalize, final circuit -> out.
// ---------------------------------------------------------------------------

#define B 32
#define S 2048
#define NTOK (B * S)          // 65536
#define KSPLIT 16
#define KCHUNK (S / KSPLIT)   // 128 keys per block
#define NPAIR (KCHUNK / 2)    // 64 key pairs
#define QPT 4                 // queries per thread
#define QTILE (128 * QPT)     // 512 queries per block

__device__ float g_Q[NTOK * 4];
__device__ float g_K[NTOK * 4];
__device__ float g_V[NTOK * 4];
__device__ float4 g_p0[NTOK * KSPLIT];   // (ssum, a0, a1, a2)
__device__ float  g_p1[NTOK * KSPLIT];   // a3
__device__ float2 g_w[16];               // cos/sin(w/2): [0..3]=Q,[4..7]=K,[8..11]=V,[12..15]=C

typedef unsigned long long u64;

__device__ __forceinline__ u64 mul2(u64 a, u64 b) {
    u64 d; asm("mul.rn.f32x2 %0,%1,%2;" : "=l"(d) : "l"(a), "l"(b)); return d;
}
__device__ __forceinline__ u64 fma2(u64 a, u64 b, u64 c) {
    u64 d; asm("fma.rn.f32x2 %0,%1,%2,%3;" : "=l"(d) : "l"(a), "l"(b), "l"(c)); return d;
}
__device__ __forceinline__ u64 add2(u64 a, u64 b) {
    u64 d; asm("add.rn.f32x2 %0,%1,%2;" : "=l"(d) : "l"(a), "l"(b)); return d;
}
__device__ __forceinline__ float2 u2f(u64 u) {
    float2 f; asm("mov.b64 {%0,%1}, %2;" : "=f"(f.x), "=f"(f.y) : "l"(u)); return f;
}
__device__ __forceinline__ u64 f2u(float a, float b) {
    u64 u; asm("mov.b64 %0, {%1,%2};" : "=l"(u) : "f"(a), "f"(b)); return u;
}

// Both-keys exp2 in one MUFU op: f32x2 -> f16x2 -> ex2 -> two f32.
__device__ __forceinline__ u64 exp2_pair(u64 d2) {
    float2 df = u2f(d2);
    unsigned int hd, he;
    asm("cvt.rn.f16x2.f32 %0, %1, %2;" : "=r"(hd) : "f"(df.y), "f"(df.x));
    asm("ex2.approx.f16x2 %0, %1;" : "=r"(he) : "r"(hd));
    float ea, eb;
    asm("{ .reg .b16 l,h;\n\t"
        "  mov.b32 {l,h}, %2;\n\t"
        "  cvt.f32.f16 %0, l;\n\t"
        "  cvt.f32.f16 %1, h; }"
        : "=f"(ea), "=f"(eb) : "r"(he));
    return f2u(ea, eb);
}

// Real Givens rotation for RX on amplitude-mask M.
template <int M>
__device__ __forceinline__ void rx_real(float u[16], float c, float s) {
#pragma unroll
    for (int i = 0; i < 16; ++i) {
        if (i & M) continue;
        const int j = i | M;
        float ui = u[i], uj = u[j];
        u[i] = c * ui - s * uj;
        u[j] = c * uj + s * ui;
    }
}

// Circuit with precomputed weight cos/sin (wcs[q] = {cos, sin} of w_q/2).
__device__ __forceinline__ void run_circuit(const float ac[4], const float as_[4],
                                            const float2 wcs[4], float out[4]) {
    float u[16];
#pragma unroll
    for (int i = 0; i < 16; ++i) u[i] = 0.0f;
    u[0] = 1.0f;

    rx_real<8>(u, ac[0], as_[0]);
    rx_real<4>(u, ac[1], as_[1]);
    rx_real<2>(u, ac[2], as_[2]);
    rx_real<1>(u, ac[3], as_[3]);
    rx_real<8>(u, wcs[0].x, wcs[0].y);
    rx_real<4>(u, wcs[1].x, wcs[1].y);
    rx_real<2>(u, wcs[2].x, wcs[2].y);
    rx_real<1>(u, wcs[3].x, wcs[3].y);

#define SWAP_AMP(a, b) { float t = u[a]; u[a] = u[b]; u[b] = t; }
    SWAP_AMP(8, 12)  SWAP_AMP(9, 13)  SWAP_AMP(10, 14) SWAP_AMP(11, 15)   // CNOT(0,1)
    SWAP_AMP(4, 6)   SWAP_AMP(5, 7)   SWAP_AMP(12, 14) SWAP_AMP(13, 15)   // CNOT(1,2)
    SWAP_AMP(2, 3)   SWAP_AMP(6, 7)   SWAP_AMP(10, 11) SWAP_AMP(14, 15)   // CNOT(2,3)
    SWAP_AMP(1, 9)   SWAP_AMP(3, 11)  SWAP_AMP(5, 13)  SWAP_AMP(7, 15)    // CNOT(3,0)
#undef SWAP_AMP

    float p[16];
#pragma unroll
    for (int i = 0; i < 16; ++i) p[i] = u[i] * u[i];

    float a0 = p[0] + p[1],   d0 = p[0] - p[1];
    float a1 = p[2] + p[3],   d1 = p[2] - p[3];
    float a2 = p[4] + p[5],   d2 = p[4] - p[5];
    float a3 = p[6] + p[7],   d3 = p[6] - p[7];
    float a4 = p[8] + p[9],   d4 = p[8] - p[9];
    float a5 = p[10] + p[11], d5 = p[10] - p[11];
    float a6 = p[12] + p[13], d6 = p[12] - p[13];
    float a7 = p[14] + p[15], d7 = p[14] - p[15];
    out[3] = ((d0 + d1) + (d2 + d3)) + ((d4 + d5) + (d6 + d7));
    float b0 = a0 + a1, e0 = a0 - a1;
    float b1 = a2 + a3, e1 = a2 - a3;
    float b2 = a4 + a5, e2 = a4 - a5;
    float b3 = a6 + a7, e3 = a6 - a7;
    out[2] = (e0 + e1) + (e2 + e3);
    float c0 = b0 + b1, f0 = b0 - b1;
    float c1 = b2 + b3, f1 = b2 - b3;
    out[1] = f0 + f1;
    out[0] = c0 - c1;
}

// ---------------------------------------------------------------------------
// K0: precompute cos/sin of all uniform weights (one warp).
// ---------------------------------------------------------------------------
__global__ void prep_kernel(const float* __restrict__ wQ, const float* __restrict__ wK,
                            const float* __restrict__ wV, const float* __restrict__ wC) {
    int i = threadIdx.x;       // 0..15
    if (i < 16) {
        const float* src = (i < 4) ? wQ : (i < 8) ? wK : (i < 12) ? wV : wC;
        float ang = 0.5f * src[i & 3];
        float c, s;
        __sincosf(ang, &s, &c);
        g_w[i] = make_float2(c, s);
    }
}

// ---------------------------------------------------------------------------
// K1: token circuits. blockIdx.y selects which of {Q,K,V}.
// ---------------------------------------------------------------------------
__global__ void __launch_bounds__(128) qkv_kernel(const float4* __restrict__ x) {
    const int t = blockIdx.x * 128 + threadIdx.x;
    const int which = blockIdx.y;

    float4 a = x[t];
    float ac[4], as_[4];
    __sincosf(0.5f * a.x, &as_[0], &ac[0]);
    __sincosf(0.5f * a.y, &as_[1], &ac[1]);
    __sincosf(0.5f * a.z, &as_[2], &ac[2]);
    __sincosf(0.5f * a.w, &as_[3], &ac[3]);

    float* dst = (which == 0) ? g_Q : (which == 1) ? g_K : g_V;
    const float scale = (which == 0) ? (0.5f * 1.4426950408889634f) : 1.0f;

    float2 wcs[4];
#pragma unroll
    for (int q = 0; q < 4; ++q) wcs[q] = g_w[which * 4 + q];

    float o[4];
    run_circuit(ac, as_, wcs, o);
    reinterpret_cast<float4*>(dst)[t] =
        make_float4(o[0] * scale, o[1] * scale, o[2] * scale, o[3] * scale);
}

// ---------------------------------------------------------------------------
// K2: attention partials. grid (B, S/QTILE, KSPLIT/2), launched twice with
// kq_base 0 and KSPLIT/2 (position #4 in the launch sequence = attn for ncu).
// smem pre-packed key-pair transposed tiles (f32x2 words):
//   s_kxy[p] = { (kx[2p],kx[2p+1]), (ky[2p],ky[2p+1]) }, s_kzw/s_vxy/s_vzw same.
// Mainloop per (2 keys x 4 queries): 4 LDS.128, 16 fma2, 4 add2, 4 f16x2-EX2.
// ---------------------------------------------------------------------------
__global__ void __launch_bounds__(128) attn_kernel(int kq_base) {
    __shared__ ulonglong2 s_kxy[NPAIR], s_kzw[NPAIR], s_vxy[NPAIR], s_vzw[NPAIR];

    const int b  = blockIdx.x;
    const int qb = blockIdx.y * QTILE;
    const int kq = kq_base + blockIdx.z;
    const int t  = threadIdx.x;
    const int w  = t >> 5, lane = t & 31;

    // Fill transposed pre-packed tiles: warp w builds array w; lane handles
    // pairs (lane, lane+32). NPAIR == 64.
    {
        const float4* src = ((w < 2) ? reinterpret_cast<const float4*>(g_K)
                                     : reinterpret_cast<const float4*>(g_V))
                            + b * S + kq * KCHUNK;
        ulonglong2* dst = (w == 0) ? s_kxy : (w == 1) ? s_kzw
                        : (w == 2) ? s_vxy : s_vzw;
#pragma unroll
        for (int pp = lane; pp < NPAIR; pp += 32) {
            float4 k0 = src[2 * pp];
            float4 k1 = src[2 * pp + 1];
            ulonglong2 pk;
            if (w & 1) { pk.x = f2u(k0.z, k1.z); pk.y = f2u(k0.w, k1.w); }
            else       { pk.x = f2u(k0.x, k1.x); pk.y = f2u(k0.y, k1.y); }
            dst[pp] = pk;
        }
    }

    // Queries: duplicate each component into both f32x2 lanes (one-time cost).
    u64 qx[QPT], qy[QPT], qz[QPT], qw[QPT];
    u64 ax[QPT], ay[QPT], az[QPT], aw[QPT], ss[QPT];
#pragma unroll
    for (int j = 0; j < QPT; ++j) {
        float4 qv = reinterpret_cast<const float4*>(g_Q)[b * S + qb + t + j * 128];
        qx[j] = f2u(qv.x, qv.x);
        qy[j] = f2u(qv.y, qv.y);
        qz[j] = f2u(qv.z, qv.z);
        qw[j] = f2u(qv.w, qv.w);
        ax[j] = ay[j] = az[j] = aw[j] = ss[j] = f2u(0.f, 0.f);
    }

    __syncthreads();

#pragma unroll 4
    for (int p = 0; p < NPAIR; ++p) {
        ulonglong2 kxy = s_kxy[p];   // LDS.128 broadcast, lands as f32x2 pairs
        ulonglong2 kzw = s_kzw[p];
        ulonglong2 vxy = s_vxy[p];
        ulonglong2 vzw = s_vzw[p];
#pragma unroll
        for (int j = 0; j < QPT; ++j) {
            u64 d2 = fma2(qw[j], kzw.y,
                     fma2(qz[j], kzw.x,
                     fma2(qy[j], kxy.y, mul2(qx[j], kxy.x))));
            u64 e2 = exp2_pair(d2);      // ONE f16x2 MUFU for both keys
            ss[j] = add2(ss[j], e2);
            ax[j] = fma2(e2, vxy.x, ax[j]);
            ay[j] = fma2(e2, vxy.y, ay[j]);
            az[j] = fma2(e2, vzw.x, az[j]);
            aw[j] = fma2(e2, vzw.y, aw[j]);
        }
    }

    const int base = ((b * KSPLIT + kq) << 11) + qb + t;
#pragma unroll
    for (int j = 0; j < QPT; ++j) {
        float2 sx = u2f(ss[j]);
        float2 x0 = u2f(ax[j]), x1 = u2f(ay[j]);
        float2 x2 = u2f(az[j]), x3 = u2f(aw[j]);
        g_p0[base + j * 128] = make_float4(sx.x + sx.y, x0.x + x0.y,
                                           x1.x + x1.y, x2.x + x2.y);
        g_p1[base + j * 128] = x3.x + x3.y;
    }
}

// ---------------------------------------------------------------------------
// K3: combine KSPLIT partials, normalize, final circuit -> out.
// ---------------------------------------------------------------------------
__global__ void __launch_bounds__(128) reduce_kernel(float4* __restrict__ out) {
    int g = blockIdx.x * 128 + threadIdx.x;
    int b = g >> 11;
    int q = g & (S - 1);

    float ssum = 0.f, a0 = 0.f, a1 = 0.f, a2 = 0.f, a3 = 0.f;
#pragma unroll 8
    for (int kq = 0; kq < KSPLIT; ++kq) {
        int idx = ((b * KSPLIT + kq) << 11) + q;
        float4 p = g_p0[idx];
        ssum += p.x; a0 += p.y; a1 += p.z; a2 += p.w;
        a3 += g_p1[idx];
    }
    float inv = 1.0f / ssum;

    float cc[4], cs[4], o[4];
    __sincosf(0.5f * a0 * inv, &cs[0], &cc[0]);
    __sincosf(0.5f * a1 * inv, &cs[1], &cc[1]);
    __sincosf(0.5f * a2 * inv, &cs[2], &cc[2]);
    __sincosf(0.5f * a3 * inv, &cs[3], &cc[3]);

    float2 wcs[4];
#pragma unroll
    for (int i = 0; i < 4; ++i) wcs[i] = g_w[12 + i];

    run_circuit(cc, cs, wcs, o);
    out[g] = make_float4(o[0], o[1], o[2], o[3]);
}

// ---------------------------------------------------------------------------
extern "C" void kernel_launch(void* const* d_in, const int* in_sizes, int n_in,
                              void* d_out, int out_size) {
    (void)in_sizes; (void)n_in; (void)out_size;
    const float4* x  = (const float4*)d_in[0];
    const float*  wQ = (const float*)d_in[1];
    const float*  wK = (const float*)d_in[2];
    const float*  wV = (const float*)d_in[3];
    const float*  wC = (const float*)d_in[4];

    prep_kernel<<<1, 32>>>(wQ, wK, wV, wC);
    qkv_kernel<<<dim3(NTOK / 128, 3), 128>>>(x);
    attn_kernel<<<dim3(B, S / QTILE, KSPLIT / 2), 128>>>(0);            // launch #3
    attn_kernel<<<dim3(B, S / QTILE, KSPLIT / 2), 128>>>(KSPLIT / 2);   // launch #4 -> ncu
    reduce_kernel<<<NTOK / 128, 128>>>((float4*)d_out);
}